// round 2
// baseline (speedup 1.0000x reference)
#include <cuda_runtime.h>

typedef unsigned long long ULL;

#define HF 50
#define NPIX 2500
#define NA 22500      // anchors per batch image
#define NB 8
#define NC 512
#define PRE_NMS 6000
#define POST_NMS 300

// ---------------- scratch (device globals; allocation is forbidden) ----------------
__device__ float g_conv1[NB * NC * NPIX];     // relu(conv3x3) activations [b][oc][px]
__device__ float g_boxes[NB * NA * 4];        // decoded+clipped boxes (y1,x1,y2,x2)
__device__ float g_scores[NB * NA];           // masked fg scores (-1e9 = invalid)
__device__ int   g_sel[NB * PRE_NMS];         // top-6000 anchor indices per batch

// ---------------- packed fp32x2 helpers ----------------
__device__ __forceinline__ ULL fma2(ULL a, ULL b, ULL c) {
    ULL d;
    asm("fma.rn.f32x2 %0, %1, %2, %3;" : "=l"(d) : "l"(a), "l"(b), "l"(c));
    return d;
}
__device__ __forceinline__ ULL dup2(float v) {
    ULL r;
    asm("mov.b64 %0, {%1, %1};" : "=l"(r) : "f"(v));
    return r;
}

// =====================================================================
// Kernel 1: 3x3 conv 512->512, SAME pad, + bias + relu
// grid: (pixblk=10, ocblk=8, batch=8), block 256
// block tile: 64 oc x 256 px ; thread tile: 8 oc (4 f32x2 pairs) x 8 px
// =====================================================================
#define CIC 8

__global__ void __launch_bounds__(256, 2)
k_conv(const float* __restrict__ feat, const float* __restrict__ W1,
       const float* __restrict__ b1) {
    __shared__ __align__(16) float s_in[CIC * 9 * 52];   // [ic][rowm 0..8][col 0..51]
    __shared__ __align__(16) float s_w[72 * 66];         // [t=ic*9+k][oc 0..63] pitch 66

    const int tid  = threadIdx.x;
    const int lane = tid & 31;
    const int wid  = tid >> 5;            // warp id = oc group (8 oc each)
    const int oc0  = blockIdx.y * 64;
    const int b    = blockIdx.z;
    const int p0   = blockIdx.x * 256;
    const int r0   = p0 / 50;

    // per-thread pixel smem bases
    int basej[8];
    #pragma unroll
    for (int j = 0; j < 8; j++) {
        int p = p0 + lane + 32 * j;
        if (p < NPIX) {
            int r = p / 50, c = p % 50;
            basej[j] = (r - r0) * 52 + c;
        } else {
            basej[j] = 0;
        }
    }

    ULL acc[32];
    #pragma unroll
    for (int k = 0; k < 32; k++) acc[k] = 0ULL;

    const float* featb = feat + (size_t)b * NC * NPIX;

    for (int chunk = 0; chunk < NC / CIC; chunk++) {
        const int ic0 = chunk * CIC;
        __syncthreads();
        // stage input: rows r0-1 .. r0+7, cols -1..50, zero padded
        for (int e = tid; e < CIC * 9 * 52; e += 256) {
            int ic  = e / 468;
            int rem = e - ic * 468;
            int m   = rem / 52;
            int col = rem - m * 52;
            int gr = r0 - 1 + m;
            int gc = col - 1;
            float v = 0.f;
            if (gr >= 0 && gr < 50 && gc >= 0 && gc < 50)
                v = featb[(ic0 + ic) * NPIX + gr * 50 + gc];
            s_in[e] = v;
        }
        // stage weights, transposed to [t][oc]
        for (int e = tid; e < 64 * 72; e += 256) {
            int oc_i = e / 72;
            int t    = e - oc_i * 72;
            s_w[t * 66 + oc_i] = W1[(size_t)(oc0 + oc_i) * 4608 + ic0 * 9 + t];
        }
        __syncthreads();

        #pragma unroll 1
        for (int ic = 0; ic < CIC; ic++) {
            const float* inb = s_in + ic * 468;
            #pragma unroll
            for (int kk = 0; kk < 9; kk++) {
                const int koff = (kk / 3) * 52 + (kk % 3);
                const int t = ic * 9 + kk;
                const ULL* wrow = (const ULL*)(s_w + t * 66 + wid * 8);
                ULL w0 = wrow[0], w1 = wrow[1], w2 = wrow[2], w3 = wrow[3];
                #pragma unroll
                for (int j = 0; j < 8; j++) {
                    ULL vv = dup2(inb[basej[j] + koff]);
                    acc[j * 4 + 0] = fma2(vv, w0, acc[j * 4 + 0]);
                    acc[j * 4 + 1] = fma2(vv, w1, acc[j * 4 + 1]);
                    acc[j * 4 + 2] = fma2(vv, w2, acc[j * 4 + 2]);
                    acc[j * 4 + 3] = fma2(vv, w3, acc[j * 4 + 3]);
                }
            }
        }
    }

    // epilogue: bias + relu + store
    float bias[8];
    #pragma unroll
    for (int q = 0; q < 8; q++) bias[q] = b1[oc0 + wid * 8 + q];

    #pragma unroll
    for (int j = 0; j < 8; j++) {
        int p = p0 + lane + 32 * j;
        if (p >= NPIX) continue;
        #pragma unroll
        for (int q = 0; q < 4; q++) {
            unsigned lo = (unsigned)(acc[j * 4 + q] & 0xFFFFFFFFULL);
            unsigned hi = (unsigned)(acc[j * 4 + q] >> 32);
            float v0 = fmaxf(__uint_as_float(lo) + bias[2 * q], 0.f);
            float v1 = fmaxf(__uint_as_float(hi) + bias[2 * q + 1], 0.f);
            int oc = oc0 + wid * 8 + 2 * q;
            g_conv1[((size_t)b * NC + oc) * NPIX + p]     = v0;
            g_conv1[((size_t)b * NC + oc + 1) * NPIX + p] = v1;
        }
    }
}

// =====================================================================
// Kernel 2: 1x1 heads (36 reg + 18 cls) + softmax + anchor decode
// grid: (row=50, batch=8), block 256
// =====================================================================
__global__ void __launch_bounds__(256)
k_head(const float* __restrict__ Wreg, const float* __restrict__ breg,
       const float* __restrict__ Wcls, const float* __restrict__ bcls) {
    __shared__ float xs[64 * 50];   // [ic][px]
    __shared__ float ws[64 * 54];   // [ic][out]
    __shared__ float so[54 * 50];   // [out][px]

    const int row = blockIdx.x;
    const int b   = blockIdx.y;
    const int tid = threadIdx.x;

    const int px = tid % 50;
    const int og = tid / 50;                  // 0..5 (5 is idle)
    const int o0 = og * 11;
    const int nout = (og == 4) ? 10 : 11;
    const bool active = (og < 5);

    float acc[11];
    #pragma unroll
    for (int k = 0; k < 11; k++) acc[k] = 0.f;

    for (int chunk = 0; chunk < 8; chunk++) {
        const int ic0 = chunk * 64;
        __syncthreads();
        for (int e = tid; e < 64 * 50; e += 256)
            xs[e] = g_conv1[((size_t)b * NC + ic0 + e / 50) * NPIX + row * 50 + (e % 50)];
        for (int e = tid; e < 64 * 54; e += 256) {
            int ic = e / 54, o = e % 54;
            ws[ic * 54 + o] = (o < 36) ? Wreg[o * NC + ic0 + ic]
                                       : Wcls[(o - 36) * NC + ic0 + ic];
        }
        __syncthreads();
        if (active) {
            for (int ic = 0; ic < 64; ic++) {
                float v = xs[ic * 50 + px];
                #pragma unroll
                for (int k = 0; k < 11; k++)
                    if (k < nout) acc[k] = __fmaf_rn(ws[ic * 54 + o0 + k], v, acc[k]);
            }
        }
    }
    __syncthreads();
    if (active)
        for (int k = 0; k < nout; k++) so[(o0 + k) * 50 + px] = acc[k];
    __syncthreads();

    const float RAT[3] = {0.5f, 1.f, 2.f};
    const float SCL[3] = {8.f, 16.f, 32.f};

    for (int t = tid; t < 450; t += 256) {
        int a = t % 9;
        int j = t / 9;
        int ri = a / 3, si = a % 3;

        float dy = __fadd_rn(so[(4 * a + 0) * 50 + j], breg[4 * a + 0]);
        float dx = __fadd_rn(so[(4 * a + 1) * 50 + j], breg[4 * a + 1]);
        float dh = __fadd_rn(so[(4 * a + 2) * 50 + j], breg[4 * a + 2]);
        float dw = __fadd_rn(so[(4 * a + 3) * 50 + j], breg[4 * a + 3]);
        float l0 = __fadd_rn(so[(36 + 2 * a) * 50 + j], bcls[2 * a]);
        float l1 = __fadd_rn(so[(36 + 2 * a + 1) * 50 + j], bcls[2 * a + 1]);

        // softmax fg prob (2-class, max-subtracted, jax style)
        float m  = fmaxf(l0, l1);
        float e0 = expf(__fsub_rn(l0, m));
        float e1 = expf(__fsub_rn(l1, m));
        float fg = __fdiv_rn(e1, __fadd_rn(e0, e1));

        // anchor geometry (replicating reference fp32 op order)
        float ha  = __fmul_rn(__fmul_rn(16.f, SCL[si]), sqrtf(RAT[ri]));
        float wa  = __fmul_rn(__fmul_rn(16.f, SCL[si]), sqrtf(__fdiv_rn(1.f, RAT[ri])));
        float cy0 = 16.f * (float)(row + 1) - 25.f;
        float cx0 = 16.f * (float)(j + 1) - 25.f;
        float ay1 = __fsub_rn(cy0, __fmul_rn(0.5f, ha));
        float ax1 = __fsub_rn(cx0, __fmul_rn(0.5f, wa));
        float ay2 = __fadd_rn(cy0, __fmul_rn(0.5f, ha));
        float ax2 = __fadd_rn(cx0, __fmul_rn(0.5f, wa));
        float ah  = __fsub_rn(ay2, ay1);
        float aw  = __fsub_rn(ax2, ax1);
        float acy = __fadd_rn(ay1, __fmul_rn(0.5f, ah));
        float acx = __fadd_rn(ax1, __fmul_rn(0.5f, aw));

        float cy = __fadd_rn(__fmul_rn(dy, ah), acy);
        float cx = __fadd_rn(__fmul_rn(dx, aw), acx);
        float hh = __fmul_rn(expf(dh), ah);
        float ww = __fmul_rn(expf(dw), aw);

        float y1 = __fsub_rn(cy, __fmul_rn(0.5f, hh));
        float x1 = __fsub_rn(cx, __fmul_rn(0.5f, ww));
        float y2 = __fadd_rn(cy, __fmul_rn(0.5f, hh));
        float x2 = __fadd_rn(cx, __fmul_rn(0.5f, ww));
        y1 = fminf(fmaxf(y1, 0.f), 800.f);
        y2 = fminf(fmaxf(y2, 0.f), 800.f);
        x1 = fminf(fmaxf(x1, 0.f), 800.f);
        x2 = fminf(fmaxf(x2, 0.f), 800.f);

        float hgt = __fsub_rn(y2, y1);
        float wdt = __fsub_rn(x2, x1);
        bool ok = (hgt >= 16.f) && (wdt >= 16.f);
        float sc = ok ? fg : -1e9f;

        int n = (row * 50 + j) * 9 + a;
        size_t off = (size_t)b * NA + n;
        g_scores[off] = sc;
        g_boxes[off * 4 + 0] = y1;
        g_boxes[off * 4 + 1] = x1;
        g_boxes[off * 4 + 2] = y2;
        g_boxes[off * 4 + 3] = x2;
    }
}

// =====================================================================
// Kernel 3: per-batch exact top-6000 via 8x8-bit radix select on
// 64-bit keys = (ordered score bits || ~anchor index)
// grid: 8 blocks, 1024 threads
// =====================================================================
__device__ __forceinline__ ULL make_key(float s, int i) {
    unsigned u = __float_as_uint(s);
    unsigned ord = (u & 0x80000000u) ? ~u : (u | 0x80000000u);
    return ((ULL)ord << 32) | (ULL)(~(unsigned)i);
}

__global__ void __launch_bounds__(1024)
k_select() {
    __shared__ unsigned h2[32 * 256];
    __shared__ unsigned histT[256];
    __shared__ ULL sh_prefix;
    __shared__ int sh_need;
    __shared__ int sh_cnt;

    const int b   = blockIdx.x;
    const int tid = threadIdx.x;
    const int wid = tid >> 5;
    const float* sc = g_scores + (size_t)b * NA;

    if (tid == 0) { sh_prefix = 0ULL; sh_need = PRE_NMS; sh_cnt = 0; }

    for (int shift = 56; shift >= 0; shift -= 8) {
        __syncthreads();
        for (int e = tid; e < 32 * 256; e += 1024) h2[e] = 0;
        __syncthreads();
        ULL pref = sh_prefix;
        for (int i = tid; i < NA; i += 1024) {
            ULL key = make_key(sc[i], i);
            // high bits (above current byte) must match prefix
            if ((((key ^ pref) >> shift) >> 8) == 0ULL)
                atomicAdd(&h2[wid * 256 + (unsigned)((key >> shift) & 255ULL)], 1u);
        }
        __syncthreads();
        if (tid < 256) {
            unsigned s = 0;
            for (int w = 0; w < 32; w++) s += h2[w * 256 + tid];
            histT[tid] = s;
        }
        __syncthreads();
        if (tid == 0) {
            int need = sh_need;
            int bin = 0;
            for (int v = 255; v >= 0; v--) {
                int c = (int)histT[v];
                if (c >= need) { bin = v; break; }
                need -= c;
            }
            sh_prefix |= ((ULL)bin << shift);
            sh_need = need;
        }
    }
    __syncthreads();
    const ULL thr = sh_prefix;   // exact 6000th-largest key
    for (int i = tid; i < NA; i += 1024) {
        if (make_key(sc[i], i) >= thr) {
            int pos = atomicAdd(&sh_cnt, 1);
            g_sel[b * PRE_NMS + pos] = i;
        }
    }
}

// =====================================================================
// Kernel 4: greedy NMS, 300 selections over 6000 candidates in smem
// grid: 8 blocks, 1024 threads, 168000B dynamic smem
// =====================================================================
__global__ void __launch_bounds__(1024)
k_nms(float* __restrict__ out) {
    extern __shared__ __align__(16) char smraw[];
    ULL*    keys  = (ULL*)smraw;                          // 6000 * 8
    float4* boxs  = (float4*)(smraw + 48000);             // 6000 * 16
    float*  areas = (float*)(smraw + 48000 + 96000);      // 6000 * 4
    __shared__ ULL wk[32];
    __shared__ int wslot[32];
    __shared__ int s_slot;
    __shared__ ULL s_key;

    const int b    = blockIdx.x;
    const int tid  = threadIdx.x;
    const int lane = tid & 31;
    const int wid  = tid >> 5;

    for (int s = tid; s < PRE_NMS; s += 1024) {
        int i = g_sel[b * PRE_NMS + s];
        keys[s] = make_key(g_scores[(size_t)b * NA + i], i);
        float4 bx = *(const float4*)&g_boxes[((size_t)b * NA + i) * 4];
        boxs[s] = bx;
        areas[s] = __fmul_rn(__fsub_rn(bx.z, bx.x), __fsub_rn(bx.w, bx.y));
    }
    __syncthreads();

    float* rois = out;                        // [8][300][5]
    float* rsc  = out + NB * POST_NMS * 5;    // [8][300]

    for (int it = 0; it < POST_NMS; it++) {
        // --- block argmax over keys ---
        ULL bk = 0ULL;
        int bs = -1;
        for (int s = tid; s < PRE_NMS; s += 1024) {
            ULL k = keys[s];
            if (k > bk) { bk = k; bs = s; }
        }
        #pragma unroll
        for (int off = 16; off; off >>= 1) {
            ULL ok2 = __shfl_down_sync(0xffffffffu, bk, off);
            int os  = __shfl_down_sync(0xffffffffu, bs, off);
            if (ok2 > bk) { bk = ok2; bs = os; }
        }
        if (lane == 0) { wk[wid] = bk; wslot[wid] = bs; }
        __syncthreads();
        if (wid == 0) {
            ULL k2 = wk[lane];
            int s2 = wslot[lane];
            #pragma unroll
            for (int off = 16; off; off >>= 1) {
                ULL ok2 = __shfl_down_sync(0xffffffffu, k2, off);
                int os  = __shfl_down_sync(0xffffffffu, s2, off);
                if (ok2 > k2) { k2 = ok2; s2 = os; }
            }
            if (lane == 0) { s_slot = s2; s_key = k2; }
        }
        __syncthreads();
        const int sel = s_slot;
        const ULL selkey = s_key;

        // decode score; validity per reference (s > NEG/2)
        unsigned ordsc = (unsigned)(selkey >> 32);
        unsigned uu = (ordsc & 0x80000000u) ? (ordsc & 0x7FFFFFFFu) : ~ordsc;
        float ssc = __uint_as_float(uu);
        bool valid = (sel >= 0) && (ssc > -5e8f);

        if (tid == 0) {
            float* rr = rois + ((size_t)b * POST_NMS + it) * 5;
            if (valid) {
                float4 bb = boxs[sel];
                rr[0] = (float)b;
                rr[1] = bb.x; rr[2] = bb.y; rr[3] = bb.z; rr[4] = bb.w;
                rsc[b * POST_NMS + it] = ssc;
            } else {
                rr[0] = rr[1] = rr[2] = rr[3] = rr[4] = 0.f;
                rsc[b * POST_NMS + it] = 0.f;
            }
            if (sel >= 0) keys[sel] = 0ULL;   // remove selected
        }
        // --- suppression ---
        if (sel >= 0) {
            float4 bb = boxs[sel];
            float ba = areas[sel];
            for (int s = tid; s < PRE_NMS; s += 1024) {
                if (keys[s] == 0ULL) continue;
                float4 cb = boxs[s];
                float yy1 = fmaxf(bb.x, cb.x);
                float xx1 = fmaxf(bb.y, cb.y);
                float yy2 = fminf(bb.z, cb.z);
                float xx2 = fminf(bb.w, cb.w);
                float ih = fmaxf(__fsub_rn(yy2, yy1), 0.f);
                float iw = fmaxf(__fsub_rn(xx2, xx1), 0.f);
                float inter = __fmul_rn(ih, iw);
                float den = __fadd_rn(__fsub_rn(__fadd_rn(ba, areas[s]), inter), 1e-9f);
                float iou = __fdiv_rn(inter, den);
                if (iou > 0.7f) keys[s] = 0ULL;
            }
        }
        __syncthreads();
    }
}

// =====================================================================
extern "C" void kernel_launch(void* const* d_in, const int* in_sizes, int n_in,
                              void* d_out, int out_size) {
    const float* feat = (const float*)d_in[0];
    const float* W1   = (const float*)d_in[1];
    const float* b1   = (const float*)d_in[2];
    const float* Wreg = (const float*)d_in[3];
    const float* breg = (const float*)d_in[4];
    const float* Wcls = (const float*)d_in[5];
    const float* bcls = (const float*)d_in[6];
    float* out = (float*)d_out;

    cudaFuncSetAttribute(k_nms, cudaFuncAttributeMaxDynamicSharedMemorySize, 168000);

    k_conv<<<dim3(10, 8, 8), 256>>>(feat, W1, b1);
    k_head<<<dim3(50, 8), 256>>>(Wreg, breg, Wcls, bcls);
    k_select<<<8, 1024>>>();
    k_nms<<<8, 1024, 168000>>>(out);
}

// round 3
// speedup vs baseline: 1.0090x; 1.0090x over previous
#include <cuda_runtime.h>

typedef unsigned long long ULL;

#define NPIX 2500
#define NA 22500
#define NB 8
#define NC 512
#define PRE_NMS 6000
#define POST_NMS 300
#define NW 94            // ceil(6000/64)

// ---------------- scratch (device globals; allocation is forbidden) ----------------
__device__ float g_conv1[NB * NC * NPIX];       // relu(conv3x3) activations [b][oc][px]
__device__ float g_boxes[NB * NA * 4];          // decoded+clipped boxes
__device__ float g_scores[NB * NA];             // masked fg scores
__device__ int   g_sel[NB * PRE_NMS];           // top-6000 anchor indices (unordered)
__device__ ULL   g_skeys[NB * PRE_NMS];         // sorted keys (desc)
__device__ float4 g_sboxes[NB * PRE_NMS];       // boxes in sorted order
__device__ float g_sareas[NB * PRE_NMS];        // areas in sorted order
__device__ ULL   g_mask[(size_t)NB * PRE_NMS * NW];  // suppression bitmap

// ---------------- packed fp32x2 helpers ----------------
__device__ __forceinline__ ULL fma2(ULL a, ULL b, ULL c) {
    ULL d;
    asm("fma.rn.f32x2 %0, %1, %2, %3;" : "=l"(d) : "l"(a), "l"(b), "l"(c));
    return d;
}

// =====================================================================
// Kernel 1: 3x3 conv 512->512 + bias + relu.
// grid (10 pxblk, 8 ocblk, 8 batch), 256 thr.
// Thread: 4 even-aligned pixel-PAIRS (packed f32x2) x 8 oc.
// Inputs via LDS.64 (dual shifted smem copies keep taps 8B-aligned);
// weights pre-duplicated {w,w} in smem, read as broadcast LDS.128.
// =====================================================================
__global__ void __launch_bounds__(256, 2)
k_conv(const float* __restrict__ feat, const float* __restrict__ W1,
       const float* __restrict__ b1) {
    extern __shared__ __align__(16) float sm[];
    float* sA  = sm;            // 8*9*52 = 3744 floats
    float* sB  = sm + 3744;     // shifted copy: sB[i] = sA[i+1]
    float* swd = sm + 7488;     // 72 * 128 floats, weights duplicated+swizzled

    const int tid  = threadIdx.x;
    const int lane = tid & 31;
    const int wid  = tid >> 5;
    const int oc0  = blockIdx.y * 64;
    const int b    = blockIdx.z;
    const int p0   = blockIdx.x * 256;
    const int r0   = p0 / 50;

    int basep[4];
    bool pvalid[4];
    #pragma unroll
    for (int jj = 0; jj < 4; jj++) {
        int pp = p0 + 2 * lane + 64 * jj;      // even => pair never crosses a row
        pvalid[jj] = (pp < NPIX);
        int r = pp / 50, cc = pp % 50;
        basep[jj] = pvalid[jj] ? (r - r0) * 52 + cc : 0;
    }

    ULL acc[32];
    #pragma unroll
    for (int k = 0; k < 32; k++) acc[k] = 0ULL;

    const float* featb = feat + (size_t)b * NC * NPIX;

    for (int chunk = 0; chunk < 64; chunk++) {
        const int ic0 = chunk * 8;
        __syncthreads();
        // input tile: rows r0-1..r0+7, cols -1..50, zero-padded; plus shifted copy
        for (int e = tid; e < 3744; e += 256) {
            int ic  = e / 468;
            int rem = e - ic * 468;
            int m   = rem / 52;
            int col = rem - m * 52;
            int gr = r0 - 1 + m;
            int gc = col - 1;
            float v = 0.f;
            if (gr >= 0 && gr < 50 && (unsigned)gc < 50u)
                v = featb[(ic0 + ic) * NPIX + gr * 50 + gc];
            sA[e] = v;
            if (e > 0) sB[e - 1] = v;
        }
        // weights duplicated: pair {w,w} for oc_i at row t=ic*9+kk,
        // float4-group-swizzled: group g=oc_i>>1 -> slot (g+t)&31
        for (int e = tid; e < 4608; e += 256) {
            int oc_i = e / 72;
            int t    = e - oc_i * 72;
            float w = W1[(size_t)(oc0 + oc_i) * 4608 + ic0 * 9 + t];
            int off = t * 128 + 4 * (((oc_i >> 1) + t) & 31) + 2 * (oc_i & 1);
            swd[off] = w;
            swd[off + 1] = w;
        }
        __syncthreads();

        #pragma unroll 1
        for (int ic = 0; ic < 8; ic++) {
            const float* a  = sA + ic * 468;
            const float* bs = sB + ic * 468;
            const float* wr = swd + ic * 9 * 128;
            #pragma unroll
            for (int kk = 0; kk < 9; kk++) {
                const int t = ic * 9 + kk;
                const float* wrow = wr + kk * 128;
                ULL wd[8];
                #pragma unroll
                for (int q = 0; q < 4; q++) {
                    int gp = ((wid * 4 + q) + t) & 31;
                    ulonglong2 wv = *(const ulonglong2*)(wrow + 4 * gp);
                    wd[2 * q]     = wv.x;
                    wd[2 * q + 1] = wv.y;
                }
                const int dr = kk / 3, dc = kk % 3;
                const float* src = (dc == 1) ? bs : a;
                const int koff = dr * 52 + ((dc == 1) ? 0 : dc);
                #pragma unroll
                for (int jj = 0; jj < 4; jj++) {
                    ULL pv = *(const ULL*)(src + basep[jj] + koff);
                    #pragma unroll
                    for (int o = 0; o < 8; o++)
                        acc[jj * 8 + o] = fma2(pv, wd[o], acc[jj * 8 + o]);
                }
            }
        }
    }

    float bias[8];
    #pragma unroll
    for (int o = 0; o < 8; o++) bias[o] = b1[oc0 + wid * 8 + o];

    #pragma unroll
    for (int jj = 0; jj < 4; jj++) {
        if (!pvalid[jj]) continue;
        int p = p0 + 2 * lane + 64 * jj;
        #pragma unroll
        for (int o = 0; o < 8; o++) {
            float lo = __uint_as_float((unsigned)(acc[jj * 8 + o] & 0xFFFFFFFFULL));
            float hi = __uint_as_float((unsigned)(acc[jj * 8 + o] >> 32));
            float2 vv;
            vv.x = fmaxf(lo + bias[o], 0.f);
            vv.y = fmaxf(hi + bias[o], 0.f);
            *(float2*)&g_conv1[((size_t)b * NC + oc0 + wid * 8 + o) * NPIX + p] = vv;
        }
    }
}

// =====================================================================
// Kernel 2: 1x1 heads + softmax + anchor decode (unchanged, bit-exact)
// =====================================================================
__global__ void __launch_bounds__(256)
k_head(const float* __restrict__ Wreg, const float* __restrict__ breg,
       const float* __restrict__ Wcls, const float* __restrict__ bcls) {
    __shared__ float xs[64 * 50];
    __shared__ float ws[64 * 54];
    __shared__ float so[54 * 50];

    const int row = blockIdx.x;
    const int b   = blockIdx.y;
    const int tid = threadIdx.x;

    const int px = tid % 50;
    const int og = tid / 50;
    const int o0 = og * 11;
    const int nout = (og == 4) ? 10 : 11;
    const bool active = (og < 5);

    float acc[11];
    #pragma unroll
    for (int k = 0; k < 11; k++) acc[k] = 0.f;

    for (int chunk = 0; chunk < 8; chunk++) {
        const int ic0 = chunk * 64;
        __syncthreads();
        for (int e = tid; e < 64 * 50; e += 256)
            xs[e] = g_conv1[((size_t)b * NC + ic0 + e / 50) * NPIX + row * 50 + (e % 50)];
        for (int e = tid; e < 64 * 54; e += 256) {
            int ic = e / 54, o = e % 54;
            ws[ic * 54 + o] = (o < 36) ? Wreg[o * NC + ic0 + ic]
                                       : Wcls[(o - 36) * NC + ic0 + ic];
        }
        __syncthreads();
        if (active) {
            for (int ic = 0; ic < 64; ic++) {
                float v = xs[ic * 50 + px];
                #pragma unroll
                for (int k = 0; k < 11; k++)
                    if (k < nout) acc[k] = __fmaf_rn(ws[ic * 54 + o0 + k], v, acc[k]);
            }
        }
    }
    __syncthreads();
    if (active)
        for (int k = 0; k < nout; k++) so[(o0 + k) * 50 + px] = acc[k];
    __syncthreads();

    const float RAT[3] = {0.5f, 1.f, 2.f};
    const float SCL[3] = {8.f, 16.f, 32.f};

    for (int t = tid; t < 450; t += 256) {
        int a = t % 9;
        int j = t / 9;
        int ri = a / 3, si = a % 3;

        float dy = __fadd_rn(so[(4 * a + 0) * 50 + j], breg[4 * a + 0]);
        float dx = __fadd_rn(so[(4 * a + 1) * 50 + j], breg[4 * a + 1]);
        float dh = __fadd_rn(so[(4 * a + 2) * 50 + j], breg[4 * a + 2]);
        float dw = __fadd_rn(so[(4 * a + 3) * 50 + j], breg[4 * a + 3]);
        float l0 = __fadd_rn(so[(36 + 2 * a) * 50 + j], bcls[2 * a]);
        float l1 = __fadd_rn(so[(36 + 2 * a + 1) * 50 + j], bcls[2 * a + 1]);

        float m  = fmaxf(l0, l1);
        float e0 = expf(__fsub_rn(l0, m));
        float e1 = expf(__fsub_rn(l1, m));
        float fg = __fdiv_rn(e1, __fadd_rn(e0, e1));

        float ha  = __fmul_rn(__fmul_rn(16.f, SCL[si]), sqrtf(RAT[ri]));
        float wa  = __fmul_rn(__fmul_rn(16.f, SCL[si]), sqrtf(__fdiv_rn(1.f, RAT[ri])));
        float cy0 = 16.f * (float)(row + 1) - 25.f;
        float cx0 = 16.f * (float)(j + 1) - 25.f;
        float ay1 = __fsub_rn(cy0, __fmul_rn(0.5f, ha));
        float ax1 = __fsub_rn(cx0, __fmul_rn(0.5f, wa));
        float ay2 = __fadd_rn(cy0, __fmul_rn(0.5f, ha));
        float ax2 = __fadd_rn(cx0, __fmul_rn(0.5f, wa));
        float ah  = __fsub_rn(ay2, ay1);
        float aw  = __fsub_rn(ax2, ax1);
        float acy = __fadd_rn(ay1, __fmul_rn(0.5f, ah));
        float acx = __fadd_rn(ax1, __fmul_rn(0.5f, aw));

        float cy = __fadd_rn(__fmul_rn(dy, ah), acy);
        float cx = __fadd_rn(__fmul_rn(dx, aw), acx);
        float hh = __fmul_rn(expf(dh), ah);
        float ww = __fmul_rn(expf(dw), aw);

        float y1 = __fsub_rn(cy, __fmul_rn(0.5f, hh));
        float x1 = __fsub_rn(cx, __fmul_rn(0.5f, ww));
        float y2 = __fadd_rn(cy, __fmul_rn(0.5f, hh));
        float x2 = __fadd_rn(cx, __fmul_rn(0.5f, ww));
        y1 = fminf(fmaxf(y1, 0.f), 800.f);
        y2 = fminf(fmaxf(y2, 0.f), 800.f);
        x1 = fminf(fmaxf(x1, 0.f), 800.f);
        x2 = fminf(fmaxf(x2, 0.f), 800.f);

        float hgt = __fsub_rn(y2, y1);
        float wdt = __fsub_rn(x2, x1);
        bool ok = (hgt >= 16.f) && (wdt >= 16.f);
        float sc = ok ? fg : -1e9f;

        int n = (row * 50 + j) * 9 + a;
        size_t off = (size_t)b * NA + n;
        g_scores[off] = sc;
        g_boxes[off * 4 + 0] = y1;
        g_boxes[off * 4 + 1] = x1;
        g_boxes[off * 4 + 2] = y2;
        g_boxes[off * 4 + 3] = x2;
    }
}

// =====================================================================
// Kernel 3: exact top-6000 radix select (64-bit key = score||~idx)
// =====================================================================
__device__ __forceinline__ ULL make_key(float s, int i) {
    unsigned u = __float_as_uint(s);
    unsigned ord = (u & 0x80000000u) ? ~u : (u | 0x80000000u);
    return ((ULL)ord << 32) | (ULL)(~(unsigned)i);
}

__global__ void __launch_bounds__(1024)
k_select() {
    __shared__ unsigned h2[32 * 256];
    __shared__ unsigned histT[256];
    __shared__ ULL sh_prefix;
    __shared__ int sh_need;
    __shared__ int sh_cnt;

    const int b   = blockIdx.x;
    const int tid = threadIdx.x;
    const int wid = tid >> 5;
    const float* sc = g_scores + (size_t)b * NA;

    if (tid == 0) { sh_prefix = 0ULL; sh_need = PRE_NMS; sh_cnt = 0; }

    for (int shift = 56; shift >= 0; shift -= 8) {
        __syncthreads();
        for (int e = tid; e < 32 * 256; e += 1024) h2[e] = 0;
        __syncthreads();
        ULL pref = sh_prefix;
        for (int i = tid; i < NA; i += 1024) {
            ULL key = make_key(sc[i], i);
            if ((((key ^ pref) >> shift) >> 8) == 0ULL)
                atomicAdd(&h2[wid * 256 + (unsigned)((key >> shift) & 255ULL)], 1u);
        }
        __syncthreads();
        if (tid < 256) {
            unsigned s = 0;
            for (int w = 0; w < 32; w++) s += h2[w * 256 + tid];
            histT[tid] = s;
        }
        __syncthreads();
        if (tid == 0) {
            int need = sh_need;
            int bin = 0;
            for (int v = 255; v >= 0; v--) {
                int c = (int)histT[v];
                if (c >= need) { bin = v; break; }
                need -= c;
            }
            sh_prefix |= ((ULL)bin << shift);
            sh_need = need;
        }
    }
    __syncthreads();
    const ULL thr = sh_prefix;
    for (int i = tid; i < NA; i += 1024) {
        if (make_key(sc[i], i) >= thr) {
            int pos = atomicAdd(&sh_cnt, 1);
            g_sel[b * PRE_NMS + pos] = i;
        }
    }
}

// =====================================================================
// Kernel 4: bitonic sort 6000 keys (pad to 8192) descending, gather boxes
// =====================================================================
__global__ void __launch_bounds__(1024)
k_sortprep() {
    extern __shared__ ULL sk[];   // 8192 keys
    const int b   = blockIdx.x;
    const int tid = threadIdx.x;

    for (int s = tid; s < 8192; s += 1024) {
        if (s < PRE_NMS) {
            int i = g_sel[b * PRE_NMS + s];
            sk[s] = make_key(g_scores[(size_t)b * NA + i], i);
        } else {
            sk[s] = 0ULL;
        }
    }
    __syncthreads();

    for (int k = 2; k <= 8192; k <<= 1) {
        for (int j = k >> 1; j > 0; j >>= 1) {
            for (int t = tid; t < 8192; t += 1024) {
                int ixj = t ^ j;
                if (ixj > t) {
                    bool desc = ((t & k) == 0);
                    ULL a = sk[t], c = sk[ixj];
                    bool swap = desc ? (a < c) : (a > c);
                    if (swap) { sk[t] = c; sk[ixj] = a; }
                }
            }
            __syncthreads();
        }
    }

    for (int s = tid; s < PRE_NMS; s += 1024) {
        ULL key = sk[s];
        int aidx = (int)(~(unsigned)key);
        g_skeys[b * PRE_NMS + s] = key;
        float4 bx = *(const float4*)&g_boxes[((size_t)b * NA + aidx) * 4];
        g_sboxes[b * PRE_NMS + s] = bx;
        g_sareas[b * PRE_NMS + s] =
            __fmul_rn(__fsub_rn(bx.z, bx.x), __fsub_rn(bx.w, bx.y));
    }
}

// =====================================================================
// Kernel 5: pairwise suppression bitmap. grid (24, 94, 8), 256 thr.
// mask[i][w] bit jj set  <=>  j=64w+jj > i, j<6000, IoU(i,j) > 0.7
// =====================================================================
__global__ void __launch_bounds__(256)
k_mask() {
    __shared__ float4 jb[64];
    __shared__ float  ja[64];
    const int b  = blockIdx.z;
    const int w  = blockIdx.y;
    const int i0 = blockIdx.x * 256;
    const int j0 = w * 64;
    const int tid = threadIdx.x;

    if (tid < 64) {
        int j = j0 + tid;
        if (j < PRE_NMS) {
            jb[tid] = g_sboxes[b * PRE_NMS + j];
            ja[tid] = g_sareas[b * PRE_NMS + j];
        } else {
            jb[tid] = make_float4(0.f, 0.f, 0.f, 0.f);
            ja[tid] = 0.f;
        }
    }
    __syncthreads();

    int i = i0 + tid;
    if (i >= PRE_NMS) return;

    ULL m = 0ULL;
    if (j0 + 63 > i) {
        float4 bi = g_sboxes[b * PRE_NMS + i];
        float ai  = g_sareas[b * PRE_NMS + i];
        #pragma unroll 4
        for (int jj = 0; jj < 64; jj++) {
            float4 cb = jb[jj];
            float yy1 = fmaxf(bi.x, cb.x);
            float xx1 = fmaxf(bi.y, cb.y);
            float yy2 = fminf(bi.z, cb.z);
            float xx2 = fminf(bi.w, cb.w);
            float ih = fmaxf(__fsub_rn(yy2, yy1), 0.f);
            float iw = fmaxf(__fsub_rn(xx2, xx1), 0.f);
            float inter = __fmul_rn(ih, iw);
            float den = __fadd_rn(__fsub_rn(__fadd_rn(ai, ja[jj]), inter), 1e-9f);
            float iou = __fdiv_rn(inter, den);
            if (iou > 0.7f && (j0 + jj) > i) m |= (1ULL << jj);
        }
    }
    g_mask[((size_t)b * PRE_NMS + i) * NW + w] = m;
}

// =====================================================================
// Kernel 6: sequential greedy fold over the bitmap. 8 blocks, 128 thr.
// =====================================================================
__global__ void __launch_bounds__(128)
k_fold(float* __restrict__ out) {
    __shared__ ULL rem[NW];
    __shared__ ULL s_live;
    const int b   = blockIdx.x;
    const int tid = threadIdx.x;

    if (tid < NW) rem[tid] = 0ULL;

    float* rois = out;                        // [8][300][5]
    float* rsc  = out + NB * POST_NMS * 5;    // [8][300]

    int count = 0;
    int c = 0;
    while (true) {
        __syncthreads();
        if (count >= POST_NMS || c >= NW) break;
        if (tid == 0) {
            ULL lv = ~rem[c];
            if (c == NW - 1) lv &= ((1ULL << 48) - 1);   // 6000 = 93*64 + 48
            s_live = lv;
        }
        __syncthreads();
        ULL live = s_live;
        if (live == 0ULL) { c++; continue; }

        int bit = __ffsll((long long)live) - 1;
        int i = c * 64 + bit;
        ULL key = g_skeys[b * PRE_NMS + i];
        unsigned ordsc = (unsigned)(key >> 32);
        unsigned uu = (ordsc & 0x80000000u) ? (ordsc & 0x7FFFFFFFu) : ~ordsc;
        float sc = __uint_as_float(uu);
        if (sc <= -5e8f) break;   // all remaining are invalid -> zero fill

        if (tid == 0) {
            float4 bb = g_sboxes[b * PRE_NMS + i];
            float* rr = rois + ((size_t)b * POST_NMS + count) * 5;
            rr[0] = (float)b;
            rr[1] = bb.x; rr[2] = bb.y; rr[3] = bb.z; rr[4] = bb.w;
            rsc[b * POST_NMS + count] = sc;
        }
        if (tid < NW) {
            ULL mm = g_mask[((size_t)b * PRE_NMS + i) * NW + tid];
            if (tid == c) mm |= (1ULL << bit);
            rem[tid] |= mm;
        }
        count++;
    }

    for (int slot = count + tid; slot < POST_NMS; slot += 128) {
        float* rr = rois + ((size_t)b * POST_NMS + slot) * 5;
        rr[0] = rr[1] = rr[2] = rr[3] = rr[4] = 0.f;
        rsc[b * POST_NMS + slot] = 0.f;
    }
}

// =====================================================================
extern "C" void kernel_launch(void* const* d_in, const int* in_sizes, int n_in,
                              void* d_out, int out_size) {
    const float* feat = (const float*)d_in[0];
    const float* W1   = (const float*)d_in[1];
    const float* b1   = (const float*)d_in[2];
    const float* Wreg = (const float*)d_in[3];
    const float* breg = (const float*)d_in[4];
    const float* Wcls = (const float*)d_in[5];
    const float* bcls = (const float*)d_in[6];
    float* out = (float*)d_out;

    const int CONV_SMEM = (3744 + 3744 + 9216) * 4;   // 66816 B
    const int SORT_SMEM = 8192 * 8;                   // 65536 B
    cudaFuncSetAttribute(k_conv, cudaFuncAttributeMaxDynamicSharedMemorySize, CONV_SMEM);
    cudaFuncSetAttribute(k_sortprep, cudaFuncAttributeMaxDynamicSharedMemorySize, SORT_SMEM);

    k_conv<<<dim3(10, 8, 8), 256, CONV_SMEM>>>(feat, W1, b1);
    k_head<<<dim3(50, 8), 256>>>(Wreg, breg, Wcls, bcls);
    k_select<<<8, 1024>>>();
    k_sortprep<<<8, 1024, SORT_SMEM>>>();
    k_mask<<<dim3(24, NW, 8), 256>>>();
    k_fold<<<8, 128>>>(out);
}